// round 9
// baseline (speedup 1.0000x reference)
#include <cuda_runtime.h>
#include <cuda_fp16.h>
#include <cstdint>

#define NN 4096
#define DD 64
#define NITER 50
#define REGI 10.0f
#define INV_REG 0.1f
#define EPSF 1e-16f
#define AB (1.0f / 4096.0f)
#define INV_SCALE (1.0f / 262144.0f)   // 2^-18
#define LN_SCALE 12.476649250079f      // 18*ln2
#define NWORK 512
#define NTHR 256
#define DSM_BYTES 34816

// ---------------- persistent device state (no cudaMalloc allowed) ----------
__device__ uint4 g_E4[(size_t)NN * NN / 8];    // E*2^18 fp16 row-major, 32 MiB
__device__ uint4 g_ET4[(size_t)NN * NN / 8];   // transpose, 32 MiB
__device__ __align__(16) float g_xs[NN], g_ys[NN];
__device__ __align__(16) float g_su[NN], g_sv[NN];
__device__ float g_part[NWORK];
__device__ unsigned g_suCnt[256];   // 8 counters, 128B apart (c*32)
__device__ unsigned g_svCnt[256];
__device__ unsigned g_buildCnt;
__device__ unsigned g_lossCnt;

extern __shared__ float dsm[];

// ---------------- sync primitives ------------------------------------------
__device__ __forceinline__ unsigned ldacq(const unsigned* p) {
    unsigned v;
    asm volatile("ld.acquire.gpu.global.u32 %0, [%1];" : "=r"(v) : "l"(p) : "memory");
    return v;
}
__device__ __forceinline__ void redrel(unsigned* p) {
    asm volatile("red.release.gpu.global.add.u32 [%0], 1;" :: "l"(p) : "memory");
}
__device__ __forceinline__ void stgrel(float* p, float v) {
    asm volatile("st.relaxed.gpu.global.f32 [%0], %1;" :: "l"(p), "f"(v) : "memory");
}
// one-lane poll for a chunk counter, warp-converged exit
__device__ __forceinline__ void wchunk(unsigned* cnt, unsigned tgt, int l) {
    if (l == 0) {
        unsigned v = ldacq(cnt);
        while (v < tgt) { __nanosleep(64); v = ldacq(cnt); }
    }
    __syncwarp();
}

// ---------------- init: norms, su, counters --------------------------------
__global__ __launch_bounds__(256) void k_init(const float* __restrict__ x,
                                              const float* __restrict__ y) {
    const int tid = threadIdx.x;
    const int b = blockIdx.x;
    const int w = tid >> 5, l = tid & 31;

    if (b == 0) {
        if (tid < 8) { g_suCnt[tid * 32] = NWORK; g_svCnt[tid * 32] = 0; }
        if (tid == 8) { g_buildCnt = 0; g_lossCnt = 0; }
    }
#pragma unroll
    for (int rr = 0; rr < 2; rr++) {
        const int row = b * 16 + rr * 8 + w;
        float2 vx = *(const float2*)(x + (size_t)row * DD + 2 * l);
        float sx = vx.x * vx.x + vx.y * vx.y;
        float2 vy = *(const float2*)(y + (size_t)row * DD + 2 * l);
        float sy = vy.x * vy.x + vy.y * vy.y;
#pragma unroll
        for (int o = 16; o; o >>= 1) {
            sx += __shfl_xor_sync(~0u, sx, o);
            sy += __shfl_xor_sync(~0u, sy, o);
        }
        if (l == 0) { g_xs[row] = sx; g_ys[row] = sy; }
    }
    if (tid < 16) g_su[b * 16 + tid] = AB;
}

// ---------------- matvec pass (dataflow-chunked) ---------------------------
// CTA owns 8 rows of Eb (rows wb*8..+8). Warp w covers the 64-col slice
// [c*512 + 64w, +64) of every chunk c. Lane: r2 = l>>3 (rows r2, r2+4),
// q = l&7 (uint4 within slice). Poll for chunk k+1 overlaps chunk k's loads.
__device__ __forceinline__ void mv_pass(const uint4* __restrict__ Eb,
                                        const float* __restrict__ gin,
                                        float* __restrict__ gout,
                                        unsigned* cntIn, unsigned tgt,
                                        unsigned* cntOut, float* red,
                                        float* outLocal,
                                        int wb, int tid, int w, int l, int par) {
    const int r2 = l >> 3, q = l & 7;
    const size_t row0 = (size_t)wb * 8;
    const uint4* e0 = Eb + (row0 + r2) * (NN / 8) + w * 8 + q;
    const uint4* e1 = e0 + 4 * (NN / 8);
    float acc0 = 0.f, acc1 = 0.f;
    int c = (wb >> 6) & 7;                      // staggered start chunk
    wchunk(cntIn + c * 32, tgt, l);
#pragma unroll
    for (int k = 0; k < 8; k++) {
        const int co = c * 64;
        uint4 ev0 = e0[co];
        uint4 ev1 = e1[co];
        const float4* vp = (const float4*)(gin + c * 512 + w * 64 + q * 8);
        float4 v0 = __ldcg(vp), v1 = __ldcg(vp + 1);
        c = (c + 1) & 7;
        if (k < 7) wchunk(cntIn + c * 32, tgt, l);  // overlap with loads above
        const __half2* h0 = (const __half2*)&ev0;
        const __half2* h1 = (const __half2*)&ev1;
        float2 a;
        a = __half22float2(h0[0]); acc0 += a.x * v0.x + a.y * v0.y;
        a = __half22float2(h0[1]); acc0 += a.x * v0.z + a.y * v0.w;
        a = __half22float2(h0[2]); acc0 += a.x * v1.x + a.y * v1.y;
        a = __half22float2(h0[3]); acc0 += a.x * v1.z + a.y * v1.w;
        a = __half22float2(h1[0]); acc1 += a.x * v0.x + a.y * v0.y;
        a = __half22float2(h1[1]); acc1 += a.x * v0.z + a.y * v0.w;
        a = __half22float2(h1[2]); acc1 += a.x * v1.x + a.y * v1.y;
        a = __half22float2(h1[3]); acc1 += a.x * v1.z + a.y * v1.w;
    }
    acc0 += __shfl_xor_sync(~0u, acc0, 1);
    acc0 += __shfl_xor_sync(~0u, acc0, 2);
    acc0 += __shfl_xor_sync(~0u, acc0, 4);
    acc1 += __shfl_xor_sync(~0u, acc1, 1);
    acc1 += __shfl_xor_sync(~0u, acc1, 2);
    acc1 += __shfl_xor_sync(~0u, acc1, 4);
    if (q == 0) {
        red[par * 64 + r2 * 8 + w] = acc0;
        red[par * 64 + (r2 + 4) * 8 + w] = acc1;
    }
    __syncthreads();
    if (tid < 8) {
        float s = 0.f;
#pragma unroll
        for (int j = 0; j < 8; j++) s += red[par * 64 + tid * 8 + j];
        float val = AB / (s * INV_SCALE + EPSF);
        outLocal[tid] = val;
        stgrel(gout + row0 + tid, val);
        redrel(cntOut);
    }
}

// ---------------- persistent worker kernel ---------------------------------
__global__ __launch_bounds__(NTHR, 4) void k_persist(const float* __restrict__ x,
                                                     const float* __restrict__ y,
                                                     float* __restrict__ out) {
    const int tid = threadIdx.x;
    const int wb = blockIdx.x;
    const int w = tid >> 5, l = tid & 31;

    // ============ phase 1: build E + E^T (4096 tiles of 64x64, 8 each) =====
    {
        float* Xs = dsm;             // [64][68] transposed
        float* Ys = dsm + 64 * 68;
        const int tx = tid & 15, ty = tid >> 4;
        __half* Eh = (__half*)g_E4;
        __half* ETh = (__half*)g_ET4;
        for (int t = 0; t < 8; t++) {
            const int id = wb + t * NWORK;
            const int i0 = (id >> 6) * 64, j0 = (id & 63) * 64;
            for (int i = tid; i < 64 * 64; i += NTHR) {
                int r = i >> 6, k = i & 63;
                Xs[k * 68 + r] = x[(size_t)(i0 + r) * DD + k];
                Ys[k * 68 + r] = y[(size_t)(j0 + r) * DD + k];
            }
            __syncthreads();
            float acc[4][4] = {};
#pragma unroll 8
            for (int k = 0; k < 64; k++) {
                float4 a4 = *(const float4*)&Xs[k * 68 + ty * 4];
                float4 b4 = *(const float4*)&Ys[k * 68 + tx * 4];
                float ar[4] = {a4.x, a4.y, a4.z, a4.w};
                float br[4] = {b4.x, b4.y, b4.z, b4.w};
#pragma unroll
                for (int r = 0; r < 4; r++)
#pragma unroll
                    for (int c2 = 0; c2 < 4; c2++) acc[r][c2] += ar[r] * br[c2];
            }
            float xr[4], yc[4];
#pragma unroll
            for (int r = 0; r < 4; r++) xr[r] = __ldcg(&g_xs[i0 + ty * 4 + r]);
            {
                float4 y4 = __ldcg((const float4*)&g_ys[j0 + tx * 4]);
                yc[0] = y4.x; yc[1] = y4.y; yc[2] = y4.z; yc[3] = y4.w;
            }
            __half hv[4][4];
#pragma unroll
            for (int r = 0; r < 4; r++)
#pragma unroll
                for (int c2 = 0; c2 < 4; c2++)
                    hv[r][c2] = __float2half_rn(
                        __expf((2.f * acc[r][c2] - xr[r] - yc[c2]) * INV_REG + LN_SCALE));
#pragma unroll
            for (int r = 0; r < 4; r++) {
                union { uint2 u; __half2 h[2]; } pk;
                pk.h[0] = __halves2half2(hv[r][0], hv[r][1]);
                pk.h[1] = __halves2half2(hv[r][2], hv[r][3]);
                *(uint2*)(Eh + (size_t)(i0 + ty * 4 + r) * NN + j0 + tx * 4) = pk.u;
            }
#pragma unroll
            for (int c2 = 0; c2 < 4; c2++) {
                union { uint2 u; __half2 h[2]; } pk;
                pk.h[0] = __halves2half2(hv[0][c2], hv[1][c2]);
                pk.h[1] = __halves2half2(hv[2][c2], hv[3][c2]);
                *(uint2*)(ETh + (size_t)(j0 + tx * 4 + c2) * NN + i0 + ty * 4) = pk.u;
            }
            __syncthreads();
        }
    }
    // publish build completion; wait for all builders
    if (tid == 0) {
        asm volatile("fence.acq_rel.gpu;" ::: "memory");
        redrel(&g_buildCnt);
        unsigned v = ldacq(&g_buildCnt);
        while (v < NWORK) { __nanosleep(128); v = ldacq(&g_buildCnt); }
    }
    __syncthreads();

    float* red = dsm;          // [2][64]
    float* svL = dsm + 128;    // [8]
    float* suL = dsm + 136;    // [8]
    const int mychunk = (wb >> 6) * 32;

    // ============ phase 2: 50 Sinkhorn iterations (no global barriers) =====
    for (int it = 0; it < NITER; it++) {
        const unsigned tgt = (unsigned)NWORK * (it + 1);
        mv_pass(g_ET4, g_su, g_sv, g_suCnt, tgt, &g_svCnt[mychunk],
                red, svL, wb, tid, w, l, 0);
        mv_pass(g_E4, g_sv, g_su, g_svCnt, tgt, &g_suCnt[mychunk],
                red, suL, wb, tid, w, l, 1);
    }

    // ============ phase 3: loss over this CTA's 8 rows (no waits needed) ===
    {
        __syncthreads();
        const int r2 = l >> 3, q = l & 7;
        const size_t row0 = (size_t)wb * 8;
        const uint4* e0 = g_E4 + (row0 + r2) * (NN / 8) + w * 8 + q;
        const uint4* e1 = e0 + 4 * (NN / 8);
        float acc0 = 0.f, acc1 = 0.f;
#pragma unroll 1
        for (int c = 0; c < 8; c++) {
            uint4 ev0 = e0[c * 64];
            uint4 ev1 = e1[c * 64];
            const float4* vp = (const float4*)(g_sv + c * 512 + w * 64 + q * 8);
            float4 v0 = __ldcg(vp), v1 = __ldcg(vp + 1);
            float vv[8] = {v0.x, v0.y, v0.z, v0.w, v1.x, v1.y, v1.z, v1.w};
            const __half2* h0 = (const __half2*)&ev0;
            const __half2* h1 = (const __half2*)&ev1;
#pragma unroll
            for (int p = 0; p < 4; p++) {
                float2 a = __half22float2(h0[p]);
                float t0 = (a.x > 0.f) ? a.x * (LN_SCALE - __logf(a.x)) : 0.f;
                float t1 = (a.y > 0.f) ? a.y * (LN_SCALE - __logf(a.y)) : 0.f;
                acc0 += t0 * vv[2 * p] + t1 * vv[2 * p + 1];
                float2 b2 = __half22float2(h1[p]);
                float s0 = (b2.x > 0.f) ? b2.x * (LN_SCALE - __logf(b2.x)) : 0.f;
                float s1 = (b2.y > 0.f) ? b2.y * (LN_SCALE - __logf(b2.y)) : 0.f;
                acc1 += s0 * vv[2 * p] + s1 * vv[2 * p + 1];
            }
        }
        acc0 += __shfl_xor_sync(~0u, acc0, 1);
        acc0 += __shfl_xor_sync(~0u, acc0, 2);
        acc0 += __shfl_xor_sync(~0u, acc0, 4);
        acc1 += __shfl_xor_sync(~0u, acc1, 1);
        acc1 += __shfl_xor_sync(~0u, acc1, 2);
        acc1 += __shfl_xor_sync(~0u, acc1, 4);
        if (q == 0) {
            red[r2 * 8 + w] = acc0;
            red[(r2 + 4) * 8 + w] = acc1;
        }
        __syncthreads();
        if (tid < 8) {
            float s = 0.f;
#pragma unroll
            for (int j = 0; j < 8; j++) s += red[tid * 8 + j];
            red[96 + tid] = s * suL[tid];
        }
        __syncthreads();
        if (tid == 0) {
            float s = 0.f;
#pragma unroll
            for (int j = 0; j < 8; j++) s += red[96 + j];
            stgrel(&g_part[wb], REGI * INV_SCALE * s);
            redrel(&g_lossCnt);
        }
    }

    // ============ phase 4: CTA 0 gathers ===================================
    if (wb == 0) {
        if (tid == 0) {
            unsigned v = ldacq(&g_lossCnt);
            while (v < NWORK) { __nanosleep(128); v = ldacq(&g_lossCnt); }
        }
        __syncthreads();
        float v = __ldcg(&g_part[tid]) + __ldcg(&g_part[tid + 256]);
#pragma unroll
        for (int o = 16; o; o >>= 1) v += __shfl_xor_sync(~0u, v, o);
        if (l == 0) red[32 + w] = v;
        __syncthreads();
        if (tid == 0) {
            float s = 0.f;
#pragma unroll
            for (int j = 0; j < 8; j++) s += red[32 + j];
            out[0] = s;
        }
    }
}

// ---------------------------------------------------------------------------
extern "C" void kernel_launch(void* const* d_in, const int* in_sizes, int n_in,
                              void* d_out, int out_size) {
    const float* x = (const float*)d_in[0];
    const float* y = (const float*)d_in[1];
    float* out = (float*)d_out;

    cudaFuncSetAttribute(k_persist, cudaFuncAttributeMaxDynamicSharedMemorySize,
                         DSM_BYTES);
    k_init<<<256, 256>>>(x, y);
    k_persist<<<NWORK, NTHR, DSM_BYTES>>>(x, y, out);
}